// round 6
// baseline (speedup 1.0000x reference)
#include <cuda_runtime.h>
#include <cstddef>

#define FULL_MASK 0xffffffffu

// ---------------------------------------------------------------------------
// packed fp32x2 FMA (sm_100+): 2x fp32 FMA throughput on Blackwell
// ---------------------------------------------------------------------------
__device__ __forceinline__ float2 ffma2(float2 a, float2 b, float2 c) {
    unsigned long long ua = *reinterpret_cast<unsigned long long*>(&a);
    unsigned long long ub = *reinterpret_cast<unsigned long long*>(&b);
    unsigned long long uc = *reinterpret_cast<unsigned long long*>(&c);
    unsigned long long ud;
    asm("fma.rn.f32x2 %0, %1, %2, %3;" : "=l"(ud) : "l"(ua), "l"(ub), "l"(uc));
    return *reinterpret_cast<float2*>(&ud);
}

__device__ __forceinline__ float sigf(float x) {
    return __fdividef(1.0f, 1.0f + __expf(-x));
}
__device__ __forceinline__ float tanh_fast(float x) {
    return 2.0f * sigf(2.0f * x) - 1.0f;
}

__device__ __forceinline__ void lstm_cell(float pi, float pf, float pg, float po,
                                          float& c, float& h) {
    float gi = sigf(pi), gf = sigf(pf);
    float gg = tanh_fast(pg), go = sigf(po);
    c = gf * c + gi * gg;
    h = go * tanh_fast(c);
}

// Scratch: precomputed layer-1 input gates XG[B*T][256]  (64 MB)
__device__ float g_xg[64 * 1024 * 256];
// Per-m-tile completion flags: y = batch*8 + chunk; ready when flag[y] == 2
__device__ int g_flag[512];

// ---------------------------------------------------------------------------
// Fused kernel. blockIdx.x < 64  -> scan CTA (one batch each)
//               blockIdx.x >= 64 -> GEMM CTA (chunk-major tile order)
// Scan: round-1 structure for L1/L2 (register weights, smem-broadcast h,
//       staged pre-activations). Small layers (L3/L4/FC) are pipelined one
//       step behind and distributed into the existing 4 phases/barriers.
// ---------------------------------------------------------------------------
__global__ __launch_bounds__(256, 1) void fused_kernel(
    const float* __restrict__ X,
    const float* __restrict__ w1_ih0, const float* __restrict__ w1_hh0,
    const float* __restrict__ b1_0,
    const float* __restrict__ w1_ih1, const float* __restrict__ w1_hh1,
    const float* __restrict__ b1_1,
    const float* __restrict__ w2_ih0, const float* __restrict__ w2_hh0,
    const float* __restrict__ b2_0,
    const float* __restrict__ w2_ih1, const float* __restrict__ w2_hh1,
    const float* __restrict__ b2_1,
    const float* __restrict__ fc_w,  const float* __restrict__ fc_b,
    float* __restrict__ out)
{
    // ---------------- GEMM branch ----------------
    if (blockIdx.x >= 64) {
        __shared__ float As[16][132];
        __shared__ float Bs[16][132];
        const int gi = blockIdx.x - 64;          // 0..1023
        const int xnt = gi & 1;                  // n-tile
        const int r  = gi >> 1;                  // 0..511
        const int chunk = r >> 6;                // 0..7  (chunk-major order)
        const int batch = r & 63;
        const int y  = batch * 8 + chunk;        // m-tile id
        const int m0 = y * 128;
        const int n0 = xnt * 128;
        const int tid = threadIdx.x;
        const int tx = tid & 15;
        const int ty = tid >> 4;

        float2 c[8][4];
#pragma unroll
        for (int i = 0; i < 8; i++)
#pragma unroll
            for (int j = 0; j < 4; j++) c[i][j] = make_float2(0.f, 0.f);

        for (int k0 = 0; k0 < 512; k0 += 16) {
#pragma unroll
            for (int i = 0; i < 2; i++) {
                int idx = tid + i * 256;
                int row = idx >> 2;
                int kq  = (idx & 3) << 2;
                float4 va = *reinterpret_cast<const float4*>(&X[(size_t)(m0 + row) * 512 + k0 + kq]);
                As[kq + 0][row] = va.x; As[kq + 1][row] = va.y;
                As[kq + 2][row] = va.z; As[kq + 3][row] = va.w;
                float4 vb = *reinterpret_cast<const float4*>(&w1_ih0[(size_t)(n0 + row) * 512 + k0 + kq]);
                Bs[kq + 0][row] = vb.x; Bs[kq + 1][row] = vb.y;
                Bs[kq + 2][row] = vb.z; Bs[kq + 3][row] = vb.w;
            }
            __syncthreads();
#pragma unroll
            for (int kk = 0; kk < 16; kk++) {
                float4 a0 = *reinterpret_cast<const float4*>(&As[kk][ty * 8]);
                float4 a1 = *reinterpret_cast<const float4*>(&As[kk][ty * 8 + 4]);
                float4 b0 = *reinterpret_cast<const float4*>(&Bs[kk][tx * 8]);
                float4 b1 = *reinterpret_cast<const float4*>(&Bs[kk][tx * 8 + 4]);
                float  a[8]  = {a0.x, a0.y, a0.z, a0.w, a1.x, a1.y, a1.z, a1.w};
                float2 b2[4] = {make_float2(b0.x, b0.y), make_float2(b0.z, b0.w),
                                make_float2(b1.x, b1.y), make_float2(b1.z, b1.w)};
#pragma unroll
                for (int i = 0; i < 8; i++) {
                    float2 aa = make_float2(a[i], a[i]);
#pragma unroll
                    for (int j = 0; j < 4; j++)
                        c[i][j] = ffma2(aa, b2[j], c[i][j]);
                }
            }
            __syncthreads();
        }

        float4 bv0 = *reinterpret_cast<const float4*>(&b1_0[n0 + tx * 8]);
        float4 bv1 = *reinterpret_cast<const float4*>(&b1_0[n0 + tx * 8 + 4]);
#pragma unroll
        for (int i = 0; i < 8; i++) {
            int m = m0 + ty * 8 + i;
            float4 o0 = make_float4(c[i][0].x + bv0.x, c[i][0].y + bv0.y,
                                    c[i][1].x + bv0.z, c[i][1].y + bv0.w);
            float4 o1 = make_float4(c[i][2].x + bv1.x, c[i][2].y + bv1.y,
                                    c[i][3].x + bv1.z, c[i][3].y + bv1.w);
            *reinterpret_cast<float4*>(&g_xg[(size_t)m * 256 + n0 + tx * 8])     = o0;
            *reinterpret_cast<float4*>(&g_xg[(size_t)m * 256 + n0 + tx * 8 + 4]) = o1;
        }
        __syncthreads();
        if (tid == 0) {
            __threadfence();
            atomicAdd(&g_flag[y], 1);
        }
        return;
    }

    // ---------------- scan branch ----------------
    __shared__ float  sh_h1[64];
    __shared__ float  sh_h2[64];
    __shared__ float  sh_pre[256];
    __shared__ float  sh_h3[2][8];          // double-buffered by step parity
    __shared__ float  sh_h4[2][8];
    __shared__ float  sh_pre3[24];          // L3 input-projection sums
    __shared__ float  sh_pre4[24];          // L4 pre-activations
    __shared__ float2 sh_w2ih0g[768];       // == w2_ih0 as float2 (linear copy)
    __shared__ float  sh_w2hh0r[144];       // row-major 24x6
    __shared__ float  sh_w2ih1r[144];
    __shared__ float  sh_w2hh1r[144];
    __shared__ float  sh_fcw[36];           // row-major 6x6
    __shared__ float  sh_b20[24];
    __shared__ float  sh_b21[24];
    __shared__ float  sh_fcb[8];

    const int t = threadIdx.x;   // gate id for layers 1 & 2
    const int b = blockIdx.x;    // batch
    const int yb = b * 8;        // flag base for this batch

    // register-resident recurrent weights (fully unrolled -> stays in regs)
    float2 wA[32], wB[32], wC[32];
    {
        const float2* pa = reinterpret_cast<const float2*>(w1_hh0) + t * 32;
        const float2* pb = reinterpret_cast<const float2*>(w1_ih1) + t * 32;
        const float2* pc = reinterpret_cast<const float2*>(w1_hh1) + t * 32;
#pragma unroll
        for (int i = 0; i < 32; i++) { wA[i] = pa[i]; wB[i] = pb[i]; wC[i] = pc[i]; }
    }
    const float bias11 = b1_1[t];

    // ---- init shared state / small-layer weights ----
    if (t < 64) { sh_h1[t] = 0.f; sh_h2[t] = 0.f; }
    if (t < 8)  { sh_h3[0][t] = 0.f; sh_h3[1][t] = 0.f;
                  sh_h4[0][t] = 0.f; sh_h4[1][t] = 0.f;
                  sh_fcb[t] = (t < 6) ? fc_b[t] : 0.f; }
    {
        const float2* p2 = reinterpret_cast<const float2*>(w2_ih0);
        for (int i = t; i < 768; i += 256) sh_w2ih0g[i] = p2[i];
    }
    if (t < 144) {
        sh_w2hh0r[t] = w2_hh0[t];
        sh_w2ih1r[t] = w2_ih1[t];
        sh_w2hh1r[t] = w2_hh1[t];
    }
    if (t < 36) sh_fcw[t] = fc_w[t];
    if (t < 24) { sh_b20[t] = b2_0[t]; sh_b21[t] = b2_1[t]; }

    // wait for chunk 0 of this batch (both n-tiles)
    if (t == 0) {
        while (atomicAdd(&g_flag[yb], 0) < 2) __nanosleep(64);
        __threadfence();
    }
    __syncthreads();

    float c1 = 0.f, c2 = 0.f, c3 = 0.f, c4 = 0.f;
    const float* xg = g_xg + ((size_t)b << 10) * 256;
    float*      outp = out + ((size_t)b << 10) * 6;
    float xg_next = xg[t];

    // pipeline: iter 'step' computes L1/L2(step), L3/L4(step-1), FC-out(step-2)
    for (int step = 0; step <= 1025; step++) {
        const bool mainwork  = (step < 1024);
        const bool smallwork = (step >= 1) && (step <= 1024);
        const int  p   = (step - 1) & 1;     // write parity for h3/h4 (step s=step-1)
        const int  pold = p ^ 1;

        // chunk-boundary gate for the prefetch of step+1
        if (((step + 1) & 127) == 0 && step < 1023) {
            if (t == 0) {
                int yc = yb + ((step + 1) >> 7);
                while (atomicAdd(&g_flag[yc], 0) < 2) __nanosleep(64);
                __threadfence();
            }
            __syncthreads();
        }
        float xg_cur = xg_next;
        if (step < 1023) xg_next = __ldg(&xg[(size_t)(step + 1) * 256 + t]);

        // ================= phase 1 =================
        // mains: L1 pre-activations = Whh0 @ h1 + xg
        if (mainwork) {
            float2 acc0 = make_float2(0.f, 0.f), acc1 = make_float2(0.f, 0.f);
            const float4* hp = reinterpret_cast<const float4*>(sh_h1);
#pragma unroll
            for (int k4 = 0; k4 < 16; k4 += 2) {
                float4 ha = hp[k4];
                float4 hb = hp[k4 + 1];
                acc0 = ffma2(wA[2 * k4 + 0], make_float2(ha.x, ha.y), acc0);
                acc1 = ffma2(wA[2 * k4 + 1], make_float2(ha.z, ha.w), acc1);
                acc0 = ffma2(wA[2 * k4 + 2], make_float2(hb.x, hb.y), acc0);
                acc1 = ffma2(wA[2 * k4 + 3], make_float2(hb.z, hb.w), acc1);
            }
            sh_pre[t] = acc0.x + acc0.y + acc1.x + acc1.y + xg_cur;
        }
        // small: L3 input projection W2ih0 @ h2(s), 24 gates x 8-lane segments
        if (smallwork && t < 192) {
            const int gate = t >> 3, e = t & 7;
            const float2* wr = sh_w2ih0g + t * 4;
            const float2* h2p = reinterpret_cast<const float2*>(sh_h2) + e * 4;
            float2 a0 = ffma2(wr[0], h2p[0], make_float2(0.f, 0.f));
            float2 a1 = ffma2(wr[1], h2p[1], make_float2(0.f, 0.f));
            a0 = ffma2(wr[2], h2p[2], a0);
            a1 = ffma2(wr[3], h2p[3], a1);
            float v = (a0.x + a0.y) + (a1.x + a1.y);
            v += __shfl_xor_sync(FULL_MASK, v, 4, 8);
            v += __shfl_xor_sync(FULL_MASK, v, 2, 8);
            v += __shfl_xor_sync(FULL_MASK, v, 1, 8);
            if (e == 0) sh_pre3[gate] = v;
        }
        // FC output for step-2 (h4[(step-2)&1] stable during this phase)
        if (step >= 2 && t >= 224 && t < 230) {
            const int j = t - 224;
            const float* h4o = sh_h4[step & 1];     // (step-2)&1 == step&1
            float o = sh_fcb[j];
#pragma unroll
            for (int k = 0; k < 6; k++) o += sh_fcw[j * 6 + k] * h4o[k];
            outp[(size_t)(step - 2) * 6 + j] = o;
        }
        __syncthreads();   // S1

        // ================= phase 3 =================
        float p2 = 0.f;
        if (mainwork) {
            if (t < 64) {
                float gi = sigf(sh_pre[t]);
                float gf = sigf(sh_pre[64 + t]);
                float gg = tanh_fast(sh_pre[128 + t]);
                float go = sigf(sh_pre[192 + t]);
                c1 = gf * c1 + gi * gg;
                sh_h1[t] = go * tanh_fast(c1);
            }
            float2 acc0 = make_float2(0.f, 0.f), acc1 = make_float2(0.f, 0.f);
            const float4* hp = reinterpret_cast<const float4*>(sh_h2);
#pragma unroll
            for (int k4 = 0; k4 < 16; k4 += 2) {
                float4 ha = hp[k4];
                float4 hb = hp[k4 + 1];
                acc0 = ffma2(wC[2 * k4 + 0], make_float2(ha.x, ha.y), acc0);
                acc1 = ffma2(wC[2 * k4 + 1], make_float2(ha.z, ha.w), acc1);
                acc0 = ffma2(wC[2 * k4 + 2], make_float2(hb.x, hb.y), acc0);
                acc1 = ffma2(wC[2 * k4 + 3], make_float2(hb.z, hb.w), acc1);
            }
            p2 = acc0.x + acc0.y + acc1.x + acc1.y;
        }
        // small: L3 cell -> h3(s)
        if (smallwork && t >= 128 && t < 134) {
            const int j = t - 128;
            const float* h3o = sh_h3[pold];
            float pr[4];
#pragma unroll
            for (int g = 0; g < 4; g++) {
                const int r = g * 6 + j;
                float a = sh_pre3[r] + sh_b20[r];
#pragma unroll
                for (int k = 0; k < 6; k++) a += sh_w2hh0r[r * 6 + k] * h3o[k];
                pr[g] = a;
            }
            float h3n;
            lstm_cell(pr[0], pr[1], pr[2], pr[3], c3, h3n);
            sh_h3[p][j] = h3n;
        }
        __syncthreads();   // S2 (h1 new, h3(s) visible)

        // ================= phase 5 =================
        if (mainwork) {
            float2 acc0 = make_float2(0.f, 0.f), acc1 = make_float2(0.f, 0.f);
            const float4* hp = reinterpret_cast<const float4*>(sh_h1);
#pragma unroll
            for (int k4 = 0; k4 < 16; k4 += 2) {
                float4 ha = hp[k4];
                float4 hb = hp[k4 + 1];
                acc0 = ffma2(wB[2 * k4 + 0], make_float2(ha.x, ha.y), acc0);
                acc1 = ffma2(wB[2 * k4 + 1], make_float2(ha.z, ha.w), acc1);
                acc0 = ffma2(wB[2 * k4 + 2], make_float2(hb.x, hb.y), acc0);
                acc1 = ffma2(wB[2 * k4 + 3], make_float2(hb.z, hb.w), acc1);
            }
            sh_pre[t] = acc0.x + acc0.y + acc1.x + acc1.y + p2 + bias11;
        }
        // small: L4 pre-activations
        if (smallwork && t >= 160 && t < 184) {
            const int r = t - 160;
            const float* h3n = sh_h3[p];
            const float* h4o = sh_h4[pold];
            float a = sh_b21[r];
#pragma unroll
            for (int k = 0; k < 6; k++) {
                a += sh_w2ih1r[r * 6 + k] * h3n[k];
                a += sh_w2hh1r[r * 6 + k] * h4o[k];
            }
            sh_pre4[r] = a;
        }
        __syncthreads();   // S3

        // ================= phase 7 =================
        if (mainwork && t < 64) {
            float gi = sigf(sh_pre[t]);
            float gf = sigf(sh_pre[64 + t]);
            float gg = tanh_fast(sh_pre[128 + t]);
            float go = sigf(sh_pre[192 + t]);
            c2 = gf * c2 + gi * gg;
            sh_h2[t] = go * tanh_fast(c2);
        }
        // small: L4 cell -> h4(s)
        if (smallwork && t >= 64 && t < 70) {
            const int j = t - 64;
            float h4n;
            lstm_cell(sh_pre4[j], sh_pre4[6 + j], sh_pre4[12 + j], sh_pre4[18 + j],
                      c4, h4n);
            sh_h4[p][j] = h4n;
        }
        __syncthreads();   // S4 (h2 new, h4(s) visible)
    }
}

// ---------------------------------------------------------------------------
extern "C" void kernel_launch(void* const* d_in, const int* in_sizes, int n_in,
                              void* d_out, int out_size) {
    const float* x      = (const float*)d_in[0];
    const float* w1_ih0 = (const float*)d_in[1];
    const float* w1_hh0 = (const float*)d_in[2];
    const float* b1_0   = (const float*)d_in[3];
    const float* w1_ih1 = (const float*)d_in[4];
    const float* w1_hh1 = (const float*)d_in[5];
    const float* b1_1   = (const float*)d_in[6];
    const float* w2_ih0 = (const float*)d_in[7];
    const float* w2_hh0 = (const float*)d_in[8];
    const float* b2_0   = (const float*)d_in[9];
    const float* w2_ih1 = (const float*)d_in[10];
    const float* w2_hh1 = (const float*)d_in[11];
    const float* b2_1   = (const float*)d_in[12];
    const float* fc_w   = (const float*)d_in[13];
    const float* fc_b   = (const float*)d_in[14];
    float* out = (float*)d_out;

    // reset GEMM-tile completion flags (graph-capturable memset node)
    void* flag_ptr = nullptr;
    cudaGetSymbolAddress(&flag_ptr, g_flag);
    cudaMemsetAsync(flag_ptr, 0, 512 * sizeof(int));

    fused_kernel<<<64 + 1024, 256>>>(x, w1_ih0, w1_hh0, b1_0,
                                     w1_ih1, w1_hh1, b1_1,
                                     w2_ih0, w2_hh0, b2_0,
                                     w2_ih1, w2_hh1, b2_1,
                                     fc_w, fc_b, out);
}